// round 2
// baseline (speedup 1.0000x reference)
#include <cuda_runtime.h>
#include <cstddef>

// GALA autoencoder: 6 fused layers of out = relu((dyna .* DAD) @ (X @ W + b))
// B=1024 batch items, N=255 graph nodes.
//
// Per-layer fused kernel:
//   grid = (ceil(d_out/64), B). Each CTA owns batch item b and a 64-wide
//   column stripe. Phase 1 computes hs[255][64] = x_b @ W[:,stripe] + b into
//   shared memory (ALL 255 K-rows -> projection computed exactly once).
//   Phase 2 streams 16-wide tiles of A = dyna[b] .* DAD (mask fused at load)
//   and accumulates out[255][64] in 8x8 register tiles, then applies ReLU.

#define NN      255
#define NP      256
#define BB      1024
#define TN      64
#define TK      16
#define HS_P    68      // hs row pitch (floats): 68*4B = 272B, 16B aligned, conflict-free
#define AS_P    17      // A / X tile row pitch (floats)
#define NTHREADS 256

// smem layout (floats):
//   hs  [NP*HS_P]                       = 17408
//   As  [NP*AS_P]  (aliases Xs)         =  4352
//   Ws  [TK*HS_P]                       =  1088
#define SMEM_FLOATS (NP*HS_P + NP*AS_P + TK*HS_P)
#define SMEM_BYTES  (SMEM_FLOATS * 4)

// Ping-pong intermediates. buf0 holds width-400/100 layers, buf1 width-300.
// Static device arrays are the sanctioned scratch mechanism (no cudaMalloc).
__device__ float g_buf0[(size_t)BB * NN * 400];   // ~418 MB
__device__ float g_buf1[(size_t)BB * NN * 300];   // ~313 MB

__global__ void __launch_bounds__(NTHREADS)
gala_layer(const float* __restrict__ x,      // [B, N, d_in]
           const float* __restrict__ W,      // [d_in, d_out]
           const float* __restrict__ bias,   // [d_out]
           const float* __restrict__ dyna,   // [B, N, N]
           const float* __restrict__ dad,    // [N, N]
           float* __restrict__ out,          // [B, N, d_out]
           int d_in, int d_out)
{
    extern __shared__ float sm[];
    float* hs = sm;                       // NP * HS_P
    float* As = sm + NP * HS_P;           // NP * AS_P   (phase2) / Xs (phase1)
    float* Ws = As + NP * AS_P;           // TK * HS_P   (phase1)

    const int tid = threadIdx.x;
    const int tr  = tid >> 3;             // 0..31 : row group (8 rows each, i = tr*8+m)
    const int tc  = tid & 7;              // 0..7  : col group (8 cols each, c = tc*8+n)
    const int b   = blockIdx.y;
    const int c0  = blockIdx.x * TN;

    const int ldr = tid >> 4;             // 0..15 : loader row base
    const int ldc = tid & 15;             // 0..15 : loader col (k or jj)

    const float* xb  = x    + (size_t)b * NN * d_in;
    const float* dyb = dyna + (size_t)b * NN * NN;

    float acc[8][8];
#pragma unroll
    for (int m = 0; m < 8; m++)
#pragma unroll
        for (int n = 0; n < 8; n++) acc[m][n] = 0.f;

    // ------------------------------------------------------------------
    // Phase 1: hs[j][c] = sum_k x[b,j,k] * W[k, c0+c]   (bias added at store)
    // ------------------------------------------------------------------
    const int KT = (d_in + TK - 1) / TK;

    float xreg[16];
    float wreg[4];

    // prefetch tile 0
    {
        const int k0 = 0;
#pragma unroll
        for (int p = 0; p < 16; p++) {
            int j = ldr + p * 16;
            int k = k0 + ldc;
            xreg[p] = (j < NN && k < d_in) ? xb[(size_t)j * d_in + k] : 0.f;
        }
#pragma unroll
        for (int p = 0; p < 4; p++) {
            int idx = tid + p * 256;
            int k = idx >> 6;
            int c = idx & 63;
            wreg[p] = ((k0 + k) < d_in && (c0 + c) < d_out)
                        ? W[(size_t)(k0 + k) * d_out + c0 + c] : 0.f;
        }
    }

    for (int kt = 0; kt < KT; kt++) {
        __syncthreads();
        // store staged tile to smem
#pragma unroll
        for (int p = 0; p < 16; p++)
            As[(ldr + p * 16) * AS_P + ldc] = xreg[p];      // Xs alias
#pragma unroll
        for (int p = 0; p < 4; p++) {
            int idx = tid + p * 256;
            Ws[(idx >> 6) * HS_P + (idx & 63)] = wreg[p];
        }
        __syncthreads();

        // prefetch next tile (overlaps with compute below)
        if (kt + 1 < KT) {
            const int k0 = (kt + 1) * TK;
#pragma unroll
            for (int p = 0; p < 16; p++) {
                int j = ldr + p * 16;
                int k = k0 + ldc;
                xreg[p] = (j < NN && k < d_in) ? xb[(size_t)j * d_in + k] : 0.f;
            }
#pragma unroll
            for (int p = 0; p < 4; p++) {
                int idx = tid + p * 256;
                int k = idx >> 6;
                int c = idx & 63;
                wreg[p] = ((k0 + k) < d_in && (c0 + c) < d_out)
                            ? W[(size_t)(k0 + k) * d_out + c0 + c] : 0.f;
            }
        }

        // compute tile
#pragma unroll 4
        for (int kk = 0; kk < TK; kk++) {
            float xv[8];
#pragma unroll
            for (int m = 0; m < 8; m++)
                xv[m] = As[(tr * 8 + m) * AS_P + kk];
            const float4 w0 = *(const float4*)&Ws[kk * HS_P + tc * 8];
            const float4 w1 = *(const float4*)&Ws[kk * HS_P + tc * 8 + 4];
            const float wv[8] = {w0.x, w0.y, w0.z, w0.w, w1.x, w1.y, w1.z, w1.w};
#pragma unroll
            for (int m = 0; m < 8; m++)
#pragma unroll
                for (int n = 0; n < 8; n++)
                    acc[m][n] += xv[m] * wv[n];
        }
    }

    // epilogue 1: add bias, store hs, reset acc
    {
        float bv[8];
#pragma unroll
        for (int n = 0; n < 8; n++) {
            int c = c0 + tc * 8 + n;
            bv[n] = (c < d_out) ? bias[c] : 0.f;
        }
#pragma unroll
        for (int m = 0; m < 8; m++)
#pragma unroll
            for (int n = 0; n < 8; n++) {
                hs[(tr * 8 + m) * HS_P + tc * 8 + n] = acc[m][n] + bv[n];
                acc[m][n] = 0.f;
            }
    }

    // ------------------------------------------------------------------
    // Phase 2: acc[i][c] = sum_j (dyna[b,i,j]*dad[i,j]) * hs[j][c]
    // ------------------------------------------------------------------
    float areg[16];

    // prefetch A tile 0 (mask fused at load)
    {
        const int j0 = 0;
#pragma unroll
        for (int p = 0; p < 16; p++) {
            int i = ldr + p * 16;
            int j = j0 + ldc;
            areg[p] = (i < NN && j < NN)
                        ? dyb[i * NN + j] * dad[i * NN + j] : 0.f;
        }
    }

    for (int jt = 0; jt < 16; jt++) {
        __syncthreads();   // also makes hs visible on first iteration
#pragma unroll
        for (int p = 0; p < 16; p++)
            As[(ldr + p * 16) * AS_P + ldc] = areg[p];
        __syncthreads();

        if (jt + 1 < 16) {
            const int j0 = (jt + 1) * TK;
#pragma unroll
            for (int p = 0; p < 16; p++) {
                int i = ldr + p * 16;
                int j = j0 + ldc;
                areg[p] = (i < NN && j < NN)
                            ? dyb[i * NN + j] * dad[i * NN + j] : 0.f;
            }
        }

        const int j0 = jt * TK;
#pragma unroll 4
        for (int jj = 0; jj < TK; jj++) {
            float av[8];
#pragma unroll
            for (int m = 0; m < 8; m++)
                av[m] = As[(tr * 8 + m) * AS_P + jj];
            const float* hrow = &hs[(j0 + jj) * HS_P + tc * 8];
            const float4 h0 = *(const float4*)hrow;
            const float4 h1 = *(const float4*)(hrow + 4);
            const float hv[8] = {h0.x, h0.y, h0.z, h0.w, h1.x, h1.y, h1.z, h1.w};
#pragma unroll
            for (int m = 0; m < 8; m++)
#pragma unroll
                for (int n = 0; n < 8; n++)
                    acc[m][n] += av[m] * hv[n];
        }
    }

    // epilogue 2: ReLU + store
#pragma unroll
    for (int m = 0; m < 8; m++) {
        const int i = tr * 8 + m;
        if (i < NN) {
            const size_t base = (size_t)b * NN * d_out + (size_t)i * d_out;
#pragma unroll
            for (int n = 0; n < 8; n++) {
                const int c = c0 + tc * 8 + n;
                if (c < d_out)
                    out[base + c] = fmaxf(acc[m][n], 0.f);
            }
        }
    }
}

extern "C" void kernel_launch(void* const* d_in, const int* in_sizes, int n_in,
                              void* d_out, int out_size)
{
    (void)in_sizes; (void)n_in; (void)out_size;

    const float* H    = (const float*)d_in[0];
    const float* dyna = (const float*)d_in[1];
    const float* dads[4] = {
        (const float*)d_in[2],   // t_DADsm
        (const float*)d_in[3],   // s_DADsm
        (const float*)d_in[4],   // s_DADsp
        (const float*)d_in[5],   // t_DADsp
    };
    const float* Wt[6];
    const float* bt[6];
    for (int i = 0; i < 6; i++) {
        Wt[i] = (const float*)d_in[6 + 2 * i];
        bt[i] = (const float*)d_in[7 + 2 * i];
    }

    float *buf0, *buf1;
    cudaGetSymbolAddress((void**)&buf0, g_buf0);
    cudaGetSymbolAddress((void**)&buf1, g_buf1);

    cudaFuncSetAttribute(gala_layer,
                         cudaFuncAttributeMaxDynamicSharedMemorySize, SMEM_BYTES);

    const dim3 blk(NTHREADS);
    struct Layer { const float* x; int w; int dd; float* o; int din; int dout; };
    const Layer layers[6] = {
        { H,    0, 0, buf0,           2,   400 },  // t_DADsm
        { buf0, 1, 0, buf1,           400, 300 },  // t_DADsm
        { buf1, 2, 1, buf0,           300, 100 },  // s_DADsm
        { buf0, 3, 2, buf1,           100, 300 },  // s_DADsp
        { buf1, 4, 3, buf0,           300, 400 },  // t_DADsp
        { buf0, 5, 3, (float*)d_out,  400, 2   },  // t_DADsp
    };

    for (int l = 0; l < 6; l++) {
        const Layer& L = layers[l];
        dim3 grd((L.dout + TN - 1) / TN, BB);
        gala_layer<<<grd, blk, SMEM_BYTES>>>(L.x, Wt[L.w], bt[L.w],
                                             dyna, dads[L.dd], L.o,
                                             L.din, L.dout);
    }
}

// round 4
// speedup vs baseline: 1.2242x; 1.2242x over previous
#include <cuda_runtime.h>
#include <cstddef>

// GALA autoencoder: 6 fused layers of out = relu((dyna .* DAD) @ (X @ W + b))
// B=1024, N=255.
//
// R3: inner products use packed fma.rn.f32x2 (FFMA2) -> 2 fp32 MACs/issue,
// doubling the fp32 ceiling vs scalar FFMA (rt_SMSP=2). A-tiles stored
// k-major so operand loads are broadcast LDS.128 (smem crossbar off the
// critical path).

#define NN      255
#define NP      256
#define BB      1024
#define TN      64
#define TK      16
#define HS_P    68      // hs row pitch (floats), 16B-aligned rows
#define ASP2    260     // k-major A/X tile pitch (floats), 16B-aligned rows
#define NTHREADS 256

// smem floats: hs 256*68=17408, As_t 16*260=4160, Ws 16*68=1088
#define SMEM_FLOATS (NP*HS_P + TK*ASP2 + TK*HS_P)
#define SMEM_BYTES  (SMEM_FLOATS * 4)

__device__ float g_buf0[(size_t)BB * NN * 400];   // ~418 MB
__device__ float g_buf1[(size_t)BB * NN * 300];   // ~313 MB

typedef unsigned long long ull;

__device__ __forceinline__ ull pack_dup(float v) {
    ull r;
    asm("mov.b64 %0, {%1, %1};" : "=l"(r) : "f"(v));
    return r;
}
__device__ __forceinline__ void unpack2(ull v, float& lo, float& hi) {
    asm("mov.b64 {%0, %1}, %2;" : "=f"(lo), "=f"(hi) : "l"(v));
}
__device__ __forceinline__ void ffma2(ull& acc, ull a, ull b) {
    asm("fma.rn.f32x2 %0, %1, %2, %0;" : "+l"(acc) : "l"(a), "l"(b));
}

__global__ void __launch_bounds__(NTHREADS, 2)
gala_layer(const float* __restrict__ x,      // [B, N, d_in]
           const float* __restrict__ W,      // [d_in, d_out]
           const float* __restrict__ bias,   // [d_out]
           const float* __restrict__ dyna,   // [B, N, N]
           const float* __restrict__ dad,    // [N, N]
           float* __restrict__ out,          // [B, N, d_out]
           int d_in, int d_out)
{
    extern __shared__ float sm[];
    float* hs  = sm;                      // NP * HS_P
    float* Ast = sm + NP * HS_P;          // TK * ASP2   (k-major A / X tile)
    float* Ws  = Ast + TK * ASP2;         // TK * HS_P

    const int tid = threadIdx.x;
    const int tr  = tid >> 3;             // 0..31 : row group (i = tr*8+m)
    const int tc  = tid & 7;              // 0..7  : col group (c = tc*8+n)
    const int b   = blockIdx.y;
    const int c0  = blockIdx.x * TN;

    const int ldr = tid >> 4;             // 0..15
    const int ldc = tid & 15;             // 0..15

    const float* xb  = x    + (size_t)b * NN * d_in;
    const float* dyb = dyna + (size_t)b * NN * NN;

    // packed accumulators: acc2[m][n2] = (acc[m][2n2], acc[m][2n2+1])
    ull acc2[8][4];
#pragma unroll
    for (int m = 0; m < 8; m++)
#pragma unroll
        for (int n2 = 0; n2 < 4; n2++) acc2[m][n2] = 0ull;

    // ------------------------------------------------------------------
    // Phase 1: hs[j][c] = sum_k x[b,j,k] * W[k, c0+c]
    // ------------------------------------------------------------------
    const int KT = (d_in + TK - 1) / TK;

    float xreg[16];
    float wreg[4];

    {   // prefetch tile 0
        const int k0 = 0;
#pragma unroll
        for (int p = 0; p < 16; p++) {
            int j = ldr + p * 16;
            int k = k0 + ldc;
            xreg[p] = (j < NN && k < d_in) ? xb[(size_t)j * d_in + k] : 0.f;
        }
#pragma unroll
        for (int p = 0; p < 4; p++) {
            int idx = tid + p * 256;
            int k = idx >> 6, c = idx & 63;
            wreg[p] = ((k0 + k) < d_in && (c0 + c) < d_out)
                        ? W[(size_t)(k0 + k) * d_out + c0 + c] : 0.f;
        }
    }

    for (int kt = 0; kt < KT; kt++) {
        __syncthreads();
        // k-major store: Ast[k][j]
#pragma unroll
        for (int p = 0; p < 16; p++)
            Ast[ldc * ASP2 + ldr + p * 16] = xreg[p];
#pragma unroll
        for (int p = 0; p < 4; p++) {
            int idx = tid + p * 256;
            Ws[(idx >> 6) * HS_P + (idx & 63)] = wreg[p];
        }
        __syncthreads();

        if (kt + 1 < KT) {
            const int k0 = (kt + 1) * TK;
#pragma unroll
            for (int p = 0; p < 16; p++) {
                int j = ldr + p * 16;
                int k = k0 + ldc;
                xreg[p] = (j < NN && k < d_in) ? xb[(size_t)j * d_in + k] : 0.f;
            }
#pragma unroll
            for (int p = 0; p < 4; p++) {
                int idx = tid + p * 256;
                int k = idx >> 6, c = idx & 63;
                wreg[p] = ((k0 + k) < d_in && (c0 + c) < d_out)
                            ? W[(size_t)(k0 + k) * d_out + c0 + c] : 0.f;
            }
        }

#pragma unroll 4
        for (int kk = 0; kk < TK; kk++) {
            const float4 a0 = *(const float4*)&Ast[kk * ASP2 + tr * 8];
            const float4 a1 = *(const float4*)&Ast[kk * ASP2 + tr * 8 + 4];
            ull xx[8];
            xx[0] = pack_dup(a0.x); xx[1] = pack_dup(a0.y);
            xx[2] = pack_dup(a0.z); xx[3] = pack_dup(a0.w);
            xx[4] = pack_dup(a1.x); xx[5] = pack_dup(a1.y);
            xx[6] = pack_dup(a1.z); xx[7] = pack_dup(a1.w);
            const ulonglong2 wq0 = *(const ulonglong2*)&Ws[kk * HS_P + tc * 8];
            const ulonglong2 wq1 = *(const ulonglong2*)&Ws[kk * HS_P + tc * 8 + 4];
            const ull wp[4] = {wq0.x, wq0.y, wq1.x, wq1.y};
#pragma unroll
            for (int m = 0; m < 8; m++)
#pragma unroll
                for (int n2 = 0; n2 < 4; n2++)
                    ffma2(acc2[m][n2], xx[m], wp[n2]);
        }
    }

    // epilogue 1: add bias, store hs, reset acc
    {
        float bv[8];
#pragma unroll
        for (int n = 0; n < 8; n++) {
            int c = c0 + tc * 8 + n;
            bv[n] = (c < d_out) ? bias[c] : 0.f;
        }
#pragma unroll
        for (int m = 0; m < 8; m++)
#pragma unroll
            for (int n2 = 0; n2 < 4; n2++) {
                float lo, hi;
                unpack2(acc2[m][n2], lo, hi);
                hs[(tr * 8 + m) * HS_P + tc * 8 + 2 * n2]     = lo + bv[2 * n2];
                hs[(tr * 8 + m) * HS_P + tc * 8 + 2 * n2 + 1] = hi + bv[2 * n2 + 1];
                acc2[m][n2] = 0ull;
            }
    }

    // ------------------------------------------------------------------
    // Phase 2: acc[i][c] = sum_j (dyna[b,i,j]*dad[i,j]) * hs[j][c]
    // ------------------------------------------------------------------
    float areg[16];
    {   // prefetch A tile 0 (mask fused at load)
#pragma unroll
        for (int p = 0; p < 16; p++) {
            int i = ldr + p * 16;
            int j = ldc;
            areg[p] = (i < NN && j < NN) ? dyb[i * NN + j] * dad[i * NN + j] : 0.f;
        }
    }

    for (int jt = 0; jt < 16; jt++) {
        __syncthreads();   // also publishes hs on first iteration
#pragma unroll
        for (int p = 0; p < 16; p++)
            Ast[ldc * ASP2 + ldr + p * 16] = areg[p];
        __syncthreads();

        if (jt + 1 < 16) {
            const int j0 = (jt + 1) * TK;
#pragma unroll
            for (int p = 0; p < 16; p++) {
                int i = ldr + p * 16;
                int j = j0 + ldc;
                areg[p] = (i < NN && j < NN) ? dyb[i * NN + j] * dad[i * NN + j] : 0.f;
            }
        }

        const int j0 = jt * TK;
#pragma unroll 4
        for (int jj = 0; jj < TK; jj++) {
            const float4 a0 = *(const float4*)&Ast[jj * ASP2 + tr * 8];
            const float4 a1 = *(const float4*)&Ast[jj * ASP2 + tr * 8 + 4];
            ull aa[8];
            aa[0] = pack_dup(a0.x); aa[1] = pack_dup(a0.y);
            aa[2] = pack_dup(a0.z); aa[3] = pack_dup(a0.w);
            aa[4] = pack_dup(a1.x); aa[5] = pack_dup(a1.y);
            aa[6] = pack_dup(a1.z); aa[7] = pack_dup(a1.w);
            const ulonglong2 hq0 = *(const ulonglong2*)&hs[(j0 + jj) * HS_P + tc * 8];
            const ulonglong2 hq1 = *(const ulonglong2*)&hs[(j0 + jj) * HS_P + tc * 8 + 4];
            const ull hp[4] = {hq0.x, hq0.y, hq1.x, hq1.y};
#pragma unroll
            for (int m = 0; m < 8; m++)
#pragma unroll
                for (int n2 = 0; n2 < 4; n2++)
                    ffma2(acc2[m][n2], aa[m], hp[n2]);
        }
    }

    // epilogue 2: ReLU + store
#pragma unroll
    for (int m = 0; m < 8; m++) {
        const int i = tr * 8 + m;
        if (i < NN) {
            const size_t base = (size_t)b * NN * d_out + (size_t)i * d_out;
#pragma unroll
            for (int n2 = 0; n2 < 4; n2++) {
                float lo, hi;
                unpack2(acc2[m][n2], lo, hi);
                const int c = c0 + tc * 8 + 2 * n2;
                if (c < d_out)     out[base + c]     = fmaxf(lo, 0.f);
                if (c + 1 < d_out) out[base + c + 1] = fmaxf(hi, 0.f);
            }
        }
    }
}

extern "C" void kernel_launch(void* const* d_in, const int* in_sizes, int n_in,
                              void* d_out, int out_size)
{
    (void)in_sizes; (void)n_in; (void)out_size;

    const float* H    = (const float*)d_in[0];
    const float* dyna = (const float*)d_in[1];
    const float* dads[4] = {
        (const float*)d_in[2],   // t_DADsm
        (const float*)d_in[3],   // s_DADsm
        (const float*)d_in[4],   // s_DADsp
        (const float*)d_in[5],   // t_DADsp
    };
    const float* Wt[6];
    const float* bt[6];
    for (int i = 0; i < 6; i++) {
        Wt[i] = (const float*)d_in[6 + 2 * i];
        bt[i] = (const float*)d_in[7 + 2 * i];
    }

    float *buf0, *buf1;
    cudaGetSymbolAddress((void**)&buf0, g_buf0);
    cudaGetSymbolAddress((void**)&buf1, g_buf1);

    cudaFuncSetAttribute(gala_layer,
                         cudaFuncAttributeMaxDynamicSharedMemorySize, SMEM_BYTES);

    const dim3 blk(NTHREADS);
    struct Layer { const float* x; int w; int dd; float* o; int din; int dout; };
    const Layer layers[6] = {
        { H,    0, 0, buf0,           2,   400 },  // t_DADsm
        { buf0, 1, 0, buf1,           400, 300 },  // t_DADsm
        { buf1, 2, 1, buf0,           300, 100 },  // s_DADsm
        { buf0, 3, 2, buf1,           100, 300 },  // s_DADsp
        { buf1, 4, 3, buf0,           300, 400 },  // t_DADsp
        { buf0, 5, 3, (float*)d_out,  400, 2   },  // t_DADsp
    };

    for (int l = 0; l < 6; l++) {
        const Layer& L = layers[l];
        dim3 grd((L.dout + TN - 1) / TN, BB);
        gala_layer<<<grd, blk, SMEM_BYTES>>>(L.x, Wt[L.w], bt[L.w],
                                             dyna, dads[L.dd], L.o,
                                             L.din, L.dout);
    }
}

// round 10
// speedup vs baseline: 1.2258x; 1.0013x over previous
#include <cuda_runtime.h>
#include <cstddef>

// GALA autoencoder: 6 fused layers of out = relu((dyna .* DAD) @ (X @ W + b))
// B=1024, N=255.  fp32 via packed fma.rn.f32x2.
//
// R10 = R5 design with the mask_mul coverage bug fixed (it wrote only cols
// 0..63 of each 256-wide row; now strides across all 256 columns):
//   (a) dyna*dad premultiplied once per distinct DAD into padded [256][256]
//       buffers -> phase-2 loader is 4x LDG.128/thread/tile
//   (b) all tile traffic float4-vectorized
//   (c) double-buffered smem tiles, ONE barrier per k-tile.

#define NN      255
#define NP      256
#define BB      1024
#define TN      64
#define TK      16
#define HS_P    68      // hs row pitch (floats)
#define ASP     260     // k-major tile pitch (floats), rows 16B-aligned
#define NTHREADS 256

// smem floats: hs 256*68=17408, Ast 2*16*260=8320, Ws 2*16*68=2176
#define SMEM_FLOATS (NP*HS_P + 2*TK*ASP + 2*TK*HS_P)
#define SMEM_BYTES  (SMEM_FLOATS * 4)   // 111,616 B -> 2 CTAs/SM

__device__ float g_buf0[(size_t)BB * NN * 400];        // ~418 MB
__device__ float g_buf1[(size_t)BB * NN * 300];        // ~313 MB
__device__ float g_M[4][(size_t)BB * NP * NP];         // 4 x 268 MB padded masks

typedef unsigned long long ull;

__device__ __forceinline__ ull pack_dup(float v) {
    ull r; asm("mov.b64 %0, {%1, %1};" : "=l"(r) : "f"(v)); return r;
}
__device__ __forceinline__ void unpack2(ull v, float& lo, float& hi) {
    asm("mov.b64 {%0, %1}, %2;" : "=f"(lo), "=f"(hi) : "l"(v));
}
__device__ __forceinline__ void ffma2(ull& acc, ull a, ull b) {
    asm("fma.rn.f32x2 %0, %1, %2, %0;" : "+l"(acc) : "l"(a), "l"(b));
}

// ---------------------------------------------------------------------------
// Precompute: Mp[b][i][j] = (i<NN && j<NN) ? dyna[b,i,j]*dad[i,j] : 0
// grid (BB, 16), block 256. Each block covers 16 rows; each thread owns one
// row and strides its float4 quad across ALL 256 columns (fix vs R5).
// ---------------------------------------------------------------------------
__global__ void __launch_bounds__(NTHREADS)
mask_mul(const float* __restrict__ dyna, const float* __restrict__ dad,
         float* __restrict__ Mp)
{
    const int b = blockIdx.x;
    const int i = blockIdx.y * 16 + (threadIdx.x >> 4);
    const float* dyb = dyna + (size_t)b * NN * NN;
    float* mrow = &Mp[((size_t)b * NP + i) * NP];

    for (int j4 = (threadIdx.x & 15) * 4; j4 < NP; j4 += 64) {
        float4 v;
        float* vp = (float*)&v;
#pragma unroll
        for (int q = 0; q < 4; q++) {
            int j = j4 + q;
            vp[q] = (i < NN && j < NN) ? dyb[i * NN + j] * dad[i * NN + j] : 0.f;
        }
        *(float4*)&mrow[j4] = v;
    }
}

// ---------------------------------------------------------------------------
// Fused layer
// ---------------------------------------------------------------------------
__global__ void __launch_bounds__(NTHREADS, 2)
gala_layer(const float* __restrict__ x,      // [B, N, d_in]
           const float* __restrict__ W,      // [d_in, d_out]
           const float* __restrict__ bias,   // [d_out]
           const float* __restrict__ Mp,     // [B, 256, 256] padded mask
           float* __restrict__ out,          // [B, N, d_out]
           int d_in, int d_out)
{
    extern __shared__ float sm[];
    float* hs  = sm;                        // NP*HS_P
    float* Ast = sm + NP * HS_P;            // 2 x TK*ASP  (k-major tiles)
    float* Ws  = Ast + 2 * TK * ASP;        // 2 x TK*HS_P

    const int tid = threadIdx.x;
    const int tr  = tid >> 3;               // 0..31
    const int tc  = tid & 7;                // 0..7
    const int b   = blockIdx.y;
    const int c0  = blockIdx.x * TN;

    // phase-1 X loader: jr row, kq k-quad
    const int jr = tid & 63;
    const int kq = tid >> 6;                // 0..3
    // phase-1 W loader
    const int kr = tid >> 4;                // 0..15
    const int cq = tid & 15;                // 0..15
    // phase-2 M loader
    const int ir  = tid >> 2;               // 0..63
    const int jq  = tid & 3;                // 0..3

    const float* xb  = x  + (size_t)b * NN * d_in;
    const float* Mb  = Mp + (size_t)b * NP * NP;

    ull acc2[8][4];
#pragma unroll
    for (int m = 0; m < 8; m++)
#pragma unroll
        for (int n2 = 0; n2 < 4; n2++) acc2[m][n2] = 0ull;

    // ------------------------------------------------------------------
    // Phase 1: hs[j][c] = sum_k x[b,j,k] * W[k, c0+c]
    // ------------------------------------------------------------------
    const int KT = (d_in + TK - 1) / TK;

    float4 xv[4];
    float4 wv;

    auto loadX = [&](int kt) {
        const int gk = kt * TK + kq * 4;
#pragma unroll
        for (int p = 0; p < 4; p++) {
            const int j = jr + p * 64;
            if (j < NN && gk + 4 <= d_in) {
                xv[p] = *(const float4*)&xb[(size_t)j * d_in + gk];
            } else {
                float* vp = (float*)&xv[p];
#pragma unroll
                for (int q = 0; q < 4; q++)
                    vp[q] = (j < NN && gk + q < d_in) ? xb[(size_t)j * d_in + gk + q] : 0.f;
            }
        }
    };
    auto storeX = [&](int s) {
        float* dst = Ast + s * TK * ASP;
#pragma unroll
        for (int p = 0; p < 4; p++) {
            const int j = jr + p * 64;
            const float* vp = (const float*)&xv[p];
#pragma unroll
            for (int q = 0; q < 4; q++)
                dst[(kq * 4 + q) * ASP + j] = vp[q];
        }
    };
    auto loadW = [&](int kt) {
        const int k = kt * TK + kr;
        const int c = c0 + cq * 4;
        if (k < d_in && c + 4 <= d_out) {
            wv = *(const float4*)&W[(size_t)k * d_out + c];
        } else {
            float* vp = (float*)&wv;
#pragma unroll
            for (int q = 0; q < 4; q++)
                vp[q] = (k < d_in && c + q < d_out) ? W[(size_t)k * d_out + c + q] : 0.f;
        }
    };
    auto storeW = [&](int s) {
        *(float4*)&Ws[s * TK * HS_P + kr * HS_P + cq * 4] = wv;
    };

    auto compute = [&](int s) {
        const float* At = Ast + s * TK * ASP;
        const float* Wt = Ws  + s * TK * HS_P;
#pragma unroll 4
        for (int kk = 0; kk < TK; kk++) {
            const float4 a0 = *(const float4*)&At[kk * ASP + tr * 8];
            const float4 a1 = *(const float4*)&At[kk * ASP + tr * 8 + 4];
            ull xx[8];
            xx[0] = pack_dup(a0.x); xx[1] = pack_dup(a0.y);
            xx[2] = pack_dup(a0.z); xx[3] = pack_dup(a0.w);
            xx[4] = pack_dup(a1.x); xx[5] = pack_dup(a1.y);
            xx[6] = pack_dup(a1.z); xx[7] = pack_dup(a1.w);
            const ulonglong2 w0 = *(const ulonglong2*)&Wt[kk * HS_P + tc * 8];
            const ulonglong2 w1 = *(const ulonglong2*)&Wt[kk * HS_P + tc * 8 + 4];
            const ull wp[4] = {w0.x, w0.y, w1.x, w1.y};
#pragma unroll
            for (int m = 0; m < 8; m++)
#pragma unroll
                for (int n2 = 0; n2 < 4; n2++)
                    ffma2(acc2[m][n2], xx[m], wp[n2]);
        }
    };

    loadX(0); loadW(0);
    storeX(0); storeW(0);
    __syncthreads();

    for (int kt = 0; kt < KT; kt++) {
        const int cur = kt & 1;
        const bool more = (kt + 1 < KT);
        if (more) { loadX(kt + 1); loadW(kt + 1); }
        compute(cur);
        if (more) { storeX(cur ^ 1); storeW(cur ^ 1); }
        __syncthreads();
    }

    // epilogue 1: bias, store hs, reset acc
    {
        float bv[8];
#pragma unroll
        for (int n = 0; n < 8; n++) {
            int c = c0 + tc * 8 + n;
            bv[n] = (c < d_out) ? bias[c] : 0.f;
        }
#pragma unroll
        for (int m = 0; m < 8; m++)
#pragma unroll
            for (int n2 = 0; n2 < 4; n2++) {
                float lo, hi;
                unpack2(acc2[m][n2], lo, hi);
                hs[(tr * 8 + m) * HS_P + tc * 8 + 2 * n2]     = lo + bv[2 * n2];
                hs[(tr * 8 + m) * HS_P + tc * 8 + 2 * n2 + 1] = hi + bv[2 * n2 + 1];
                acc2[m][n2] = 0ull;
            }
    }

    // ------------------------------------------------------------------
    // Phase 2: acc[i][c] = sum_j M[i][j] * hs[j][c]   (M padded, col255=0)
    // ------------------------------------------------------------------
    float4 mv[4];
    auto loadM = [&](int jt) {
        const int j = jt * TK + jq * 4;
#pragma unroll
        for (int p = 0; p < 4; p++)
            mv[p] = *(const float4*)&Mb[(size_t)(ir + p * 64) * NP + j];
    };
    auto storeM = [&](int s) {
        float* dst = Ast + s * TK * ASP;
#pragma unroll
        for (int p = 0; p < 4; p++) {
            const int i = ir + p * 64;
            const float* vp = (const float*)&mv[p];
#pragma unroll
            for (int q = 0; q < 4; q++)
                dst[(jq * 4 + q) * ASP + i] = vp[q];
        }
    };
    auto compute2 = [&](int s, int jt) {
        const float* At = Ast + s * TK * ASP;
        const float* hb = hs + (size_t)jt * TK * HS_P;
#pragma unroll 4
        for (int jj = 0; jj < TK; jj++) {
            const float4 a0 = *(const float4*)&At[jj * ASP + tr * 8];
            const float4 a1 = *(const float4*)&At[jj * ASP + tr * 8 + 4];
            ull aa[8];
            aa[0] = pack_dup(a0.x); aa[1] = pack_dup(a0.y);
            aa[2] = pack_dup(a0.z); aa[3] = pack_dup(a0.w);
            aa[4] = pack_dup(a1.x); aa[5] = pack_dup(a1.y);
            aa[6] = pack_dup(a1.z); aa[7] = pack_dup(a1.w);
            const ulonglong2 h0 = *(const ulonglong2*)&hb[jj * HS_P + tc * 8];
            const ulonglong2 h1 = *(const ulonglong2*)&hb[jj * HS_P + tc * 8 + 4];
            const ull hp[4] = {h0.x, h0.y, h1.x, h1.y};
#pragma unroll
            for (int m = 0; m < 8; m++)
#pragma unroll
                for (int n2 = 0; n2 < 4; n2++)
                    ffma2(acc2[m][n2], aa[m], hp[n2]);
        }
    };

    loadM(0);
    storeM(0);
    __syncthreads();            // publishes hs + M tile 0

    for (int jt = 0; jt < 16; jt++) {
        const int cur = jt & 1;
        const bool more = (jt + 1 < 16);
        if (more) loadM(jt + 1);
        compute2(cur, jt);
        if (more) {
            storeM(cur ^ 1);
            __syncthreads();
        }
    }

    // epilogue 2: ReLU + store (float4 when possible)
#pragma unroll
    for (int m = 0; m < 8; m++) {
        const int i = tr * 8 + m;
        if (i >= NN) continue;
        const size_t base = (size_t)b * NN * d_out + (size_t)i * d_out;
#pragma unroll
        for (int h = 0; h < 2; h++) {
            float v0, v1, v2, v3;
            unpack2(acc2[m][2 * h],     v0, v1);
            unpack2(acc2[m][2 * h + 1], v2, v3);
            const int c = c0 + tc * 8 + 4 * h;
            if (c + 4 <= d_out) {
                float4 o;
                o.x = fmaxf(v0, 0.f); o.y = fmaxf(v1, 0.f);
                o.z = fmaxf(v2, 0.f); o.w = fmaxf(v3, 0.f);
                *(float4*)&out[base + c] = o;
            } else {
                if (c     < d_out) out[base + c]     = fmaxf(v0, 0.f);
                if (c + 1 < d_out) out[base + c + 1] = fmaxf(v1, 0.f);
                if (c + 2 < d_out) out[base + c + 2] = fmaxf(v2, 0.f);
                if (c + 3 < d_out) out[base + c + 3] = fmaxf(v3, 0.f);
            }
        }
    }
}

extern "C" void kernel_launch(void* const* d_in, const int* in_sizes, int n_in,
                              void* d_out, int out_size)
{
    (void)in_sizes; (void)n_in; (void)out_size;

    const float* H    = (const float*)d_in[0];
    const float* dyna = (const float*)d_in[1];
    const float* dads[4] = {
        (const float*)d_in[2],   // t_DADsm
        (const float*)d_in[3],   // s_DADsm
        (const float*)d_in[4],   // s_DADsp
        (const float*)d_in[5],   // t_DADsp
    };
    const float* Wt[6];
    const float* bt[6];
    for (int i = 0; i < 6; i++) {
        Wt[i] = (const float*)d_in[6 + 2 * i];
        bt[i] = (const float*)d_in[7 + 2 * i];
    }

    float *buf0, *buf1, *Mbase;
    cudaGetSymbolAddress((void**)&buf0, g_buf0);
    cudaGetSymbolAddress((void**)&buf1, g_buf1);
    cudaGetSymbolAddress((void**)&Mbase, g_M);
    const size_t Msz = (size_t)BB * NP * NP;

    cudaFuncSetAttribute(gala_layer,
                         cudaFuncAttributeMaxDynamicSharedMemorySize, SMEM_BYTES);

    // precompute the 4 distinct masked adjacencies
    {
        dim3 g(BB, 16), blk(NTHREADS);
        for (int d = 0; d < 4; d++)
            mask_mul<<<g, blk>>>(dyna, dads[d], Mbase + d * Msz);
    }

    const dim3 blk(NTHREADS);
    struct Layer { const float* x; int w; int dd; float* o; int din; int dout; };
    const Layer layers[6] = {
        { H,    0, 0, buf0,           2,   400 },  // t_DADsm
        { buf0, 1, 0, buf1,           400, 300 },  // t_DADsm
        { buf1, 2, 1, buf0,           300, 100 },  // s_DADsm
        { buf0, 3, 2, buf1,           100, 300 },  // s_DADsp
        { buf1, 4, 3, buf0,           300, 400 },  // t_DADsp
        { buf0, 5, 3, (float*)d_out,  400, 2   },  // t_DADsp
    };

    for (int l = 0; l < 6; l++) {
        const Layer& L = layers[l];
        dim3 grd((L.dout + TN - 1) / TN, BB);
        gala_layer<<<grd, blk, SMEM_BYTES>>>(L.x, Wt[L.w], bt[L.w],
                                             Mbase + L.dd * Msz, L.o,
                                             L.din, L.dout);
    }
}

// round 11
// speedup vs baseline: 1.2273x; 1.0012x over previous
#include <cuda_runtime.h>
#include <cstddef>

// GALA autoencoder: 6 fused layers of out = relu((dyna .* DAD) @ (X @ W + b))
// B=1024, N=255.  fp32 via packed fma.rn.f32x2.
//
// R10 = R5 design with the mask_mul coverage bug fixed (it wrote only cols
// 0..63 of each 256-wide row; now strides across all 256 columns):
//   (a) dyna*dad premultiplied once per distinct DAD into padded [256][256]
//       buffers -> phase-2 loader is 4x LDG.128/thread/tile
//   (b) all tile traffic float4-vectorized
//   (c) double-buffered smem tiles, ONE barrier per k-tile.

#define NN      255
#define NP      256
#define BB      1024
#define TN      64
#define TK      16
#define HS_P    68      // hs row pitch (floats)
#define ASP     260     // k-major tile pitch (floats), rows 16B-aligned
#define NTHREADS 256

// smem floats: hs 256*68=17408, Ast 2*16*260=8320, Ws 2*16*68=2176
#define SMEM_FLOATS (NP*HS_P + 2*TK*ASP + 2*TK*HS_P)
#define SMEM_BYTES  (SMEM_FLOATS * 4)   // 111,616 B -> 2 CTAs/SM

__device__ float g_buf0[(size_t)BB * NN * 400];        // ~418 MB
__device__ float g_buf1[(size_t)BB * NN * 300];        // ~313 MB
__device__ float g_M[4][(size_t)BB * NP * NP];         // 4 x 268 MB padded masks

typedef unsigned long long ull;

__device__ __forceinline__ ull pack_dup(float v) {
    ull r; asm("mov.b64 %0, {%1, %1};" : "=l"(r) : "f"(v)); return r;
}
__device__ __forceinline__ void unpack2(ull v, float& lo, float& hi) {
    asm("mov.b64 {%0, %1}, %2;" : "=f"(lo), "=f"(hi) : "l"(v));
}
__device__ __forceinline__ void ffma2(ull& acc, ull a, ull b) {
    asm("fma.rn.f32x2 %0, %1, %2, %0;" : "+l"(acc) : "l"(a), "l"(b));
}

// ---------------------------------------------------------------------------
// Precompute: Mp[b][i][j] = (i<NN && j<NN) ? dyna[b,i,j]*dad[i,j] : 0
// grid (BB, 16), block 256. Each block covers 16 rows; each thread owns one
// row and strides its float4 quad across ALL 256 columns (fix vs R5).
// ---------------------------------------------------------------------------
__global__ void __launch_bounds__(NTHREADS)
mask_mul(const float* __restrict__ dyna, const float* __restrict__ dad,
         float* __restrict__ Mp)
{
    const int b = blockIdx.x;
    const int i = blockIdx.y * 16 + (threadIdx.x >> 4);
    const float* dyb = dyna + (size_t)b * NN * NN;
    float* mrow = &Mp[((size_t)b * NP + i) * NP];

    for (int j4 = (threadIdx.x & 15) * 4; j4 < NP; j4 += 64) {
        float4 v;
        float* vp = (float*)&v;
#pragma unroll
        for (int q = 0; q < 4; q++) {
            int j = j4 + q;
            vp[q] = (i < NN && j < NN) ? dyb[i * NN + j] * dad[i * NN + j] : 0.f;
        }
        *(float4*)&mrow[j4] = v;
    }
}

// ---------------------------------------------------------------------------
// Fused layer
// ---------------------------------------------------------------------------
__global__ void __launch_bounds__(NTHREADS, 2)
gala_layer(const float* __restrict__ x,      // [B, N, d_in]
           const float* __restrict__ W,      // [d_in, d_out]
           const float* __restrict__ bias,   // [d_out]
           const float* __restrict__ Mp,     // [B, 256, 256] padded mask
           float* __restrict__ out,          // [B, N, d_out]
           int d_in, int d_out)
{
    extern __shared__ float sm[];
    float* hs  = sm;                        // NP*HS_P
    float* Ast = sm + NP * HS_P;            // 2 x TK*ASP  (k-major tiles)
    float* Ws  = Ast + 2 * TK * ASP;        // 2 x TK*HS_P

    const int tid = threadIdx.x;
    const int tr  = tid >> 3;               // 0..31
    const int tc  = tid & 7;                // 0..7
    const int b   = blockIdx.y;
    const int c0  = blockIdx.x * TN;

    // phase-1 X loader: jr row, kq k-quad
    const int jr = tid & 63;
    const int kq = tid >> 6;                // 0..3
    // phase-1 W loader
    const int kr = tid >> 4;                // 0..15
    const int cq = tid & 15;                // 0..15
    // phase-2 M loader
    const int ir  = tid >> 2;               // 0..63
    const int jq  = tid & 3;                // 0..3

    const float* xb  = x  + (size_t)b * NN * d_in;
    const float* Mb  = Mp + (size_t)b * NP * NP;

    ull acc2[8][4];
#pragma unroll
    for (int m = 0; m < 8; m++)
#pragma unroll
        for (int n2 = 0; n2 < 4; n2++) acc2[m][n2] = 0ull;

    // ------------------------------------------------------------------
    // Phase 1: hs[j][c] = sum_k x[b,j,k] * W[k, c0+c]
    // ------------------------------------------------------------------
    const int KT = (d_in + TK - 1) / TK;

    float4 xv[4];
    float4 wv;

    auto loadX = [&](int kt) {
        const int gk = kt * TK + kq * 4;
#pragma unroll
        for (int p = 0; p < 4; p++) {
            const int j = jr + p * 64;
            if (j < NN && gk + 4 <= d_in) {
                xv[p] = *(const float4*)&xb[(size_t)j * d_in + gk];
            } else {
                float* vp = (float*)&xv[p];
#pragma unroll
                for (int q = 0; q < 4; q++)
                    vp[q] = (j < NN && gk + q < d_in) ? xb[(size_t)j * d_in + gk + q] : 0.f;
            }
        }
    };
    auto storeX = [&](int s) {
        float* dst = Ast + s * TK * ASP;
#pragma unroll
        for (int p = 0; p < 4; p++) {
            const int j = jr + p * 64;
            const float* vp = (const float*)&xv[p];
#pragma unroll
            for (int q = 0; q < 4; q++)
                dst[(kq * 4 + q) * ASP + j] = vp[q];
        }
    };
    auto loadW = [&](int kt) {
        const int k = kt * TK + kr;
        const int c = c0 + cq * 4;
        if (k < d_in && c + 4 <= d_out) {
            wv = *(const float4*)&W[(size_t)k * d_out + c];
        } else {
            float* vp = (float*)&wv;
#pragma unroll
            for (int q = 0; q < 4; q++)
                vp[q] = (k < d_in && c + q < d_out) ? W[(size_t)k * d_out + c + q] : 0.f;
        }
    };
    auto storeW = [&](int s) {
        *(float4*)&Ws[s * TK * HS_P + kr * HS_P + cq * 4] = wv;
    };

    auto compute = [&](int s) {
        const float* At = Ast + s * TK * ASP;
        const float* Wt = Ws  + s * TK * HS_P;
#pragma unroll 4
        for (int kk = 0; kk < TK; kk++) {
            const float4 a0 = *(const float4*)&At[kk * ASP + tr * 8];
            const float4 a1 = *(const float4*)&At[kk * ASP + tr * 8 + 4];
            ull xx[8];
            xx[0] = pack_dup(a0.x); xx[1] = pack_dup(a0.y);
            xx[2] = pack_dup(a0.z); xx[3] = pack_dup(a0.w);
            xx[4] = pack_dup(a1.x); xx[5] = pack_dup(a1.y);
            xx[6] = pack_dup(a1.z); xx[7] = pack_dup(a1.w);
            const ulonglong2 w0 = *(const ulonglong2*)&Wt[kk * HS_P + tc * 8];
            const ulonglong2 w1 = *(const ulonglong2*)&Wt[kk * HS_P + tc * 8 + 4];
            const ull wp[4] = {w0.x, w0.y, w1.x, w1.y};
#pragma unroll
            for (int m = 0; m < 8; m++)
#pragma unroll
                for (int n2 = 0; n2 < 4; n2++)
                    ffma2(acc2[m][n2], xx[m], wp[n2]);
        }
    };

    loadX(0); loadW(0);
    storeX(0); storeW(0);
    __syncthreads();

    for (int kt = 0; kt < KT; kt++) {
        const int cur = kt & 1;
        const bool more = (kt + 1 < KT);
        if (more) { loadX(kt + 1); loadW(kt + 1); }
        compute(cur);
        if (more) { storeX(cur ^ 1); storeW(cur ^ 1); }
        __syncthreads();
    }

    // epilogue 1: bias, store hs, reset acc
    {
        float bv[8];
#pragma unroll
        for (int n = 0; n < 8; n++) {
            int c = c0 + tc * 8 + n;
            bv[n] = (c < d_out) ? bias[c] : 0.f;
        }
#pragma unroll
        for (int m = 0; m < 8; m++)
#pragma unroll
            for (int n2 = 0; n2 < 4; n2++) {
                float lo, hi;
                unpack2(acc2[m][n2], lo, hi);
                hs[(tr * 8 + m) * HS_P + tc * 8 + 2 * n2]     = lo + bv[2 * n2];
                hs[(tr * 8 + m) * HS_P + tc * 8 + 2 * n2 + 1] = hi + bv[2 * n2 + 1];
                acc2[m][n2] = 0ull;
            }
    }

    // ------------------------------------------------------------------
    // Phase 2: acc[i][c] = sum_j M[i][j] * hs[j][c]   (M padded, col255=0)
    // ------------------------------------------------------------------
    float4 mv[4];
    auto loadM = [&](int jt) {
        const int j = jt * TK + jq * 4;
#pragma unroll
        for (int p = 0; p < 4; p++)
            mv[p] = *(const float4*)&Mb[(size_t)(ir + p * 64) * NP + j];
    };
    auto storeM = [&](int s) {
        float* dst = Ast + s * TK * ASP;
#pragma unroll
        for (int p = 0; p < 4; p++) {
            const int i = ir + p * 64;
            const float* vp = (const float*)&mv[p];
#pragma unroll
            for (int q = 0; q < 4; q++)
                dst[(jq * 4 + q) * ASP + i] = vp[q];
        }
    };
    auto compute2 = [&](int s, int jt) {
        const float* At = Ast + s * TK * ASP;
        const float* hb = hs + (size_t)jt * TK * HS_P;
#pragma unroll 4
        for (int jj = 0; jj < TK; jj++) {
            const float4 a0 = *(const float4*)&At[jj * ASP + tr * 8];
            const float4 a1 = *(const float4*)&At[jj * ASP + tr * 8 + 4];
            ull aa[8];
            aa[0] = pack_dup(a0.x); aa[1] = pack_dup(a0.y);
            aa[2] = pack_dup(a0.z); aa[3] = pack_dup(a0.w);
            aa[4] = pack_dup(a1.x); aa[5] = pack_dup(a1.y);
            aa[6] = pack_dup(a1.z); aa[7] = pack_dup(a1.w);
            const ulonglong2 h0 = *(const ulonglong2*)&hb[jj * HS_P + tc * 8];
            const ulonglong2 h1 = *(const ulonglong2*)&hb[jj * HS_P + tc * 8 + 4];
            const ull hp[4] = {h0.x, h0.y, h1.x, h1.y};
#pragma unroll
            for (int m = 0; m < 8; m++)
#pragma unroll
                for (int n2 = 0; n2 < 4; n2++)
                    ffma2(acc2[m][n2], aa[m], hp[n2]);
        }
    };

    loadM(0);
    storeM(0);
    __syncthreads();            // publishes hs + M tile 0

    for (int jt = 0; jt < 16; jt++) {
        const int cur = jt & 1;
        const bool more = (jt + 1 < 16);
        if (more) loadM(jt + 1);
        compute2(cur, jt);
        if (more) {
            storeM(cur ^ 1);
            __syncthreads();
        }
    }

    // epilogue 2: ReLU + store (float4 when possible)
#pragma unroll
    for (int m = 0; m < 8; m++) {
        const int i = tr * 8 + m;
        if (i >= NN) continue;
        const size_t base = (size_t)b * NN * d_out + (size_t)i * d_out;
#pragma unroll
        for (int h = 0; h < 2; h++) {
            float v0, v1, v2, v3;
            unpack2(acc2[m][2 * h],     v0, v1);
            unpack2(acc2[m][2 * h + 1], v2, v3);
            const int c = c0 + tc * 8 + 4 * h;
            if (c + 4 <= d_out) {
                float4 o;
                o.x = fmaxf(v0, 0.f); o.y = fmaxf(v1, 0.f);
                o.z = fmaxf(v2, 0.f); o.w = fmaxf(v3, 0.f);
                *(float4*)&out[base + c] = o;
            } else {
                if (c     < d_out) out[base + c]     = fmaxf(v0, 0.f);
                if (c + 1 < d_out) out[base + c + 1] = fmaxf(v1, 0.f);
                if (c + 2 < d_out) out[base + c + 2] = fmaxf(v2, 0.f);
                if (c + 3 < d_out) out[base + c + 3] = fmaxf(v3, 0.f);
            }
        }
    }
}

extern "C" void kernel_launch(void* const* d_in, const int* in_sizes, int n_in,
                              void* d_out, int out_size)
{
    (void)in_sizes; (void)n_in; (void)out_size;

    const float* H    = (const float*)d_in[0];
    const float* dyna = (const float*)d_in[1];
    const float* dads[4] = {
        (const float*)d_in[2],   // t_DADsm
        (const float*)d_in[3],   // s_DADsm
        (const float*)d_in[4],   // s_DADsp
        (const float*)d_in[5],   // t_DADsp
    };
    const float* Wt[6];
    const float* bt[6];
    for (int i = 0; i < 6; i++) {
        Wt[i] = (const float*)d_in[6 + 2 * i];
        bt[i] = (const float*)d_in[7 + 2 * i];
    }

    float *buf0, *buf1, *Mbase;
    cudaGetSymbolAddress((void**)&buf0, g_buf0);
    cudaGetSymbolAddress((void**)&buf1, g_buf1);
    cudaGetSymbolAddress((void**)&Mbase, g_M);
    const size_t Msz = (size_t)BB * NP * NP;

    cudaFuncSetAttribute(gala_layer,
                         cudaFuncAttributeMaxDynamicSharedMemorySize, SMEM_BYTES);

    // precompute the 4 distinct masked adjacencies
    {
        dim3 g(BB, 16), blk(NTHREADS);
        for (int d = 0; d < 4; d++)
            mask_mul<<<g, blk>>>(dyna, dads[d], Mbase + d * Msz);
    }

    const dim3 blk(NTHREADS);
    struct Layer { const float* x; int w; int dd; float* o; int din; int dout; };
    const Layer layers[6] = {
        { H,    0, 0, buf0,           2,   400 },  // t_DADsm
        { buf0, 1, 0, buf1,           400, 300 },  // t_DADsm
        { buf1, 2, 1, buf0,           300, 100 },  // s_DADsm
        { buf0, 3, 2, buf1,           100, 300 },  // s_DADsp
        { buf1, 4, 3, buf0,           300, 400 },  // t_DADsp
        { buf0, 5, 3, (float*)d_out,  400, 2   },  // t_DADsp
    };

    for (int l = 0; l < 6; l++) {
        const Layer& L = layers[l];
        dim3 grd((L.dout + TN - 1) / TN, BB);
        gala_layer<<<grd, blk, SMEM_BYTES>>>(L.x, Wt[L.w], bt[L.w],
                                             Mbase + L.dd * Msz, L.o,
                                             L.din, L.dout);
    }
}